// round 5
// baseline (speedup 1.0000x reference)
#include <cuda_runtime.h>
#include <math.h>

#define BATCH 8
#define CDIM  384
#define HWDIM 16384
#define HEADS 8
#define CH    48
#define EPSV  1e-12f
#define KSPLIT 8
#define KCHUNK (HWDIM / KSPLIT)   // 2048
#define NTILE  6                  // upper-triangular 128x128 tiles of 3x3

// ---------------- device scratch (no runtime allocation allowed) ------------
__device__ float g_Gp[KSPLIT*BATCH*NTILE*128*128]; // split-K Gram partials
__device__ float g_G [BATCH*CDIM*CDIM];   // Gram matrices X X^T
__device__ float g_Mq[BATCH*CDIM*CDIM];   // Wq * G
__device__ float g_Mk[BATCH*CDIM*CDIM];   // Wk * G
__device__ float g_nq[BATCH*CDIM];        // q row norms
__device__ float g_nk[BATCH*CDIM];        // k row norms
__device__ float g_At[BATCH*HEADS*CH*CH]; // softmaxed attention blocks
__device__ float g_T [BATCH*CDIM*CDIM];   // blockdiag(A) * Wv
__device__ float g_Cm[BATCH*CDIM*CDIM];   // Wo * T  (combined matrix)

__constant__ int c_ti[NTILE] = {0, 0, 0, 1, 1, 2};
__constant__ int c_tj[NTILE] = {0, 1, 2, 1, 2, 2};

// ---------------------------------------------------------------------------
// Kernel 1: Gram partials.  tile t of upper triangle, K chunk ks.
// 128x128 tile / 256 threads / 8x8 per thread / KT=16, reg-prefetch
// grid(NTILE, 1, BATCH*KSPLIT)
// NOTE: no min-blocks clause — a forced 128-reg cap risks silent acc[] spills.
// ---------------------------------------------------------------------------
__global__ __launch_bounds__(256)
void gram_kernel(const float* __restrict__ x) {
    const int tile = blockIdx.x;
    const int z    = blockIdx.z;           // b*KSPLIT + ks
    const int b    = z / KSPLIT;
    const int ks   = z % KSPLIT;
    const int i0   = c_ti[tile] * 128;
    const int j0   = c_tj[tile] * 128;
    const int kbeg = ks * KCHUNK;

    __shared__ float As[16][136];
    __shared__ float Bs[16][136];
    const float* xb = x + (size_t)b * CDIM * HWDIM;

    const int t  = threadIdx.x;            // 0..255
    const int tx = t & 15, ty = t >> 4;

    const int mA0 = (t)       >> 2, kqA0 = ((t)       & 3) << 2;
    const int mA1 = (t + 256) >> 2, kqA1 = ((t + 256) & 3) << 2;

    float acc[8][8] = {};
    float4 pa0, pa1, pb0, pb1;

    pa0 = *(const float4*)&xb[(size_t)(i0 + mA0) * HWDIM + kbeg + kqA0];
    pa1 = *(const float4*)&xb[(size_t)(i0 + mA1) * HWDIM + kbeg + kqA1];
    pb0 = *(const float4*)&xb[(size_t)(j0 + mA0) * HWDIM + kbeg + kqA0];
    pb1 = *(const float4*)&xb[(size_t)(j0 + mA1) * HWDIM + kbeg + kqA1];

    for (int k0 = kbeg; k0 < kbeg + KCHUNK; k0 += 16) {
        As[kqA0 + 0][mA0] = pa0.x; As[kqA0 + 1][mA0] = pa0.y;
        As[kqA0 + 2][mA0] = pa0.z; As[kqA0 + 3][mA0] = pa0.w;
        As[kqA1 + 0][mA1] = pa1.x; As[kqA1 + 1][mA1] = pa1.y;
        As[kqA1 + 2][mA1] = pa1.z; As[kqA1 + 3][mA1] = pa1.w;
        Bs[kqA0 + 0][mA0] = pb0.x; Bs[kqA0 + 1][mA0] = pb0.y;
        Bs[kqA0 + 2][mA0] = pb0.z; Bs[kqA0 + 3][mA0] = pb0.w;
        Bs[kqA1 + 0][mA1] = pb1.x; Bs[kqA1 + 1][mA1] = pb1.y;
        Bs[kqA1 + 2][mA1] = pb1.z; Bs[kqA1 + 3][mA1] = pb1.w;
        __syncthreads();

        int kn = k0 + 16;
        if (kn < kbeg + KCHUNK) {
            pa0 = *(const float4*)&xb[(size_t)(i0 + mA0) * HWDIM + kn + kqA0];
            pa1 = *(const float4*)&xb[(size_t)(i0 + mA1) * HWDIM + kn + kqA1];
            pb0 = *(const float4*)&xb[(size_t)(j0 + mA0) * HWDIM + kn + kqA0];
            pb1 = *(const float4*)&xb[(size_t)(j0 + mA1) * HWDIM + kn + kqA1];
        }

        #pragma unroll
        for (int kk = 0; kk < 16; kk++) {
            float a[8], bv[8];
            #pragma unroll
            for (int i = 0; i < 8; i++) a[i]  = As[kk][ty + 16 * i];
            #pragma unroll
            for (int j = 0; j < 8; j++) bv[j] = Bs[kk][tx + 16 * j];
            #pragma unroll
            for (int i = 0; i < 8; i++)
                #pragma unroll
                for (int j = 0; j < 8; j++) acc[i][j] += a[i] * bv[j];
        }
        __syncthreads();
    }

    float* Gp = g_Gp + ((size_t)z * NTILE + tile) * 16384;
    #pragma unroll
    for (int i = 0; i < 8; i++)
        #pragma unroll
        for (int j = 0; j < 8; j++)
            Gp[(ty + 16 * i) * 128 + (tx + 16 * j)] = acc[i][j];
}

// ---------------------------------------------------------------------------
// Kernel 1b: reduce split-K partials, mirror to full symmetric G.
// grid(NTILE*16384/256, BATCH), 256 threads
// ---------------------------------------------------------------------------
__global__ void gram_reduce_kernel() {
    const int b = blockIdx.y;
    const int gidx = blockIdx.x * 256 + threadIdx.x;  // tile*16384 + e
    const int tile = gidx >> 14;
    const int e    = gidx & 16383;
    const int r = e >> 7, c = e & 127;

    float s = 0.f;
    #pragma unroll
    for (int ks = 0; ks < KSPLIT; ks++)
        s += g_Gp[(((size_t)(b * KSPLIT + ks)) * NTILE + tile) * 16384 + e];

    const int i = c_ti[tile] * 128 + r;
    const int j = c_tj[tile] * 128 + c;
    float* Gb = g_G + (size_t)b * CDIM * CDIM;
    Gb[i * CDIM + j] = s;
    Gb[j * CDIM + i] = s;
}

// ---------------------------------------------------------------------------
// Generic 384x384x384 tile GEMM:  Out = A * B  (row-major)
// 64x64 tile / block(16,16) / 4x4 per thread / KT=16
// ---------------------------------------------------------------------------
__device__ __forceinline__ void mm384_tile(const float* __restrict__ A,
                                           const float* __restrict__ Bm,
                                           float* __restrict__ Out) {
    __shared__ float As[16][68];
    __shared__ float Bs[16][68];
    const int tx = threadIdx.x, ty = threadIdx.y;
    const int flat = ty * 16 + tx;
    const int i0 = blockIdx.y * 64;
    const int j0 = blockIdx.x * 64;
    float acc[4][4] = {};

    for (int k0 = 0; k0 < CDIM; k0 += 16) {
        #pragma unroll
        for (int l = 0; l < 4; l++) {
            int idx = flat + l * 256;
            As[idx & 15][idx >> 4] = A[(i0 + (idx >> 4)) * CDIM + k0 + (idx & 15)];
            Bs[idx >> 6][idx & 63]  = Bm[(k0 + (idx >> 6)) * CDIM + j0 + (idx & 63)];
        }
        __syncthreads();
        #pragma unroll
        for (int kk = 0; kk < 16; kk++) {
            float a[4], bv[4];
            #pragma unroll
            for (int i = 0; i < 4; i++) a[i]  = As[kk][ty + 16 * i];
            #pragma unroll
            for (int j = 0; j < 4; j++) bv[j] = Bs[kk][tx + 16 * j];
            #pragma unroll
            for (int i = 0; i < 4; i++)
                #pragma unroll
                for (int j = 0; j < 4; j++) acc[i][j] += a[i] * bv[j];
        }
        __syncthreads();
    }
    #pragma unroll
    for (int i = 0; i < 4; i++)
        #pragma unroll
        for (int j = 0; j < 4; j++)
            Out[(i0 + ty + 16 * i) * CDIM + (j0 + tx + 16 * j)] = acc[i][j];
}

// Kernel 2: Mq = Wq*G_b, Mk = Wk*G_b    grid(6,6, 2*BATCH)
__global__ void projG_kernel(const float* __restrict__ wq,
                             const float* __restrict__ wk) {
    const int z = blockIdx.z;
    const int b = z >> 1, s = z & 1;
    const float* W   = s ? wk : wq;
    const float* Gb  = g_G + (size_t)b * CDIM * CDIM;
    float* Out = (s ? g_Mk : g_Mq) + (size_t)b * CDIM * CDIM;
    mm384_tile(W, Gb, Out);
}

// Kernel 3: row norms   nq[i] = sqrt(sum_k Mq[i][k]*Wq[i][k])   grid(CDIM,BATCH,2)
__global__ void norm_kernel(const float* __restrict__ wq,
                            const float* __restrict__ wk) {
    const int i = blockIdx.x, b = blockIdx.y, s = blockIdx.z;
    const float* M = (s ? g_Mk : g_Mq) + ((size_t)b * CDIM + i) * CDIM;
    const float* W = (s ? wk : wq) + (size_t)i * CDIM;
    float sum = 0.f;
    for (int k = threadIdx.x; k < CDIM; k += 32) sum += M[k] * W[k];
    #pragma unroll
    for (int o = 16; o; o >>= 1) sum += __shfl_xor_sync(0xffffffffu, sum, o);
    if (threadIdx.x == 0) (s ? g_nk : g_nq)[b * CDIM + i] = sqrtf(sum);
}

// ---------------------------------------------------------------------------
// Kernel 4: attention logits (per head block, 48x48) + softmax
// grid(CH, HEADS, BATCH), block 64 (one output row per block)
// ---------------------------------------------------------------------------
__global__ void attn_kernel(const float* __restrict__ wk,
                            const float* __restrict__ temp) {
    const int i = blockIdx.x, h = blockIdx.y, b = blockIdx.z;
    const int ig = h * CH + i;
    __shared__ float mrow[CDIM];
    __shared__ float sl[CH];
    __shared__ float red[2];
    const float* Mq = g_Mq + ((size_t)b * CDIM + ig) * CDIM;
    for (int k = threadIdx.x; k < CDIM; k += 64) mrow[k] = Mq[k];
    __syncthreads();

    const int j = threadIdx.x;
    if (j < CH) {
        const int jg = h * CH + j;
        const float* wkr = wk + (size_t)jg * CDIM;
        float s = 0.f;
        #pragma unroll 8
        for (int k = 0; k < CDIM; k++) s += mrow[k] * wkr[k];
        float nq = fmaxf(g_nq[b * CDIM + ig], EPSV);
        float nk = fmaxf(g_nk[b * CDIM + jg], EPSV);
        sl[j] = s / (nq * nk) * temp[h];
    }
    __syncthreads();
    if (threadIdx.x == 0) {
        float m = -1e30f;
        for (int jj = 0; jj < CH; jj++) m = fmaxf(m, sl[jj]);
        float sum = 0.f;
        for (int jj = 0; jj < CH; jj++) sum += expf(sl[jj] - m);
        red[0] = m;
        red[1] = 1.f / sum;
    }
    __syncthreads();
    if (j < CH)
        g_At[(((size_t)b * HEADS + h) * CH + i) * CH + j] =
            expf(sl[j] - red[0]) * red[1];
}

// ---------------------------------------------------------------------------
// Kernel 5: T rows for head h:  T[h*48+i][c] = sum_j A_h[i][j] * Wv[h*48+j][c]
// grid(6 col-tiles, HEADS, BATCH), block(64,8)
// ---------------------------------------------------------------------------
__global__ void tmat_kernel(const float* __restrict__ wv) {
    const int c0 = blockIdx.x * 64, h = blockIdx.y, b = blockIdx.z;
    __shared__ float As[CH][CH];
    __shared__ float Vs[CH][64];
    const int tid = threadIdx.y * 64 + threadIdx.x;  // 512 threads
    const float* Ab = g_At + (size_t)(b * HEADS + h) * CH * CH;
    for (int idx = tid; idx < CH * CH; idx += 512)
        As[idx / CH][idx % CH] = Ab[idx];
    for (int idx = tid; idx < CH * 64; idx += 512) {
        int jj = idx >> 6, c = idx & 63;
        Vs[jj][c] = wv[(size_t)(h * CH + jj) * CDIM + c0 + c];
    }
    __syncthreads();
    const int c = threadIdx.x;
    for (int i = threadIdx.y; i < CH; i += 8) {
        float s = 0.f;
        #pragma unroll
        for (int jj = 0; jj < CH; jj++) s += As[i][jj] * Vs[jj][c];
        g_T[((size_t)b * CDIM + h * CH + i) * CDIM + c0 + c] = s;
    }
}

// Kernel 6: C_b = Wo * T_b    grid(6,6,BATCH)
__global__ void cmat_kernel(const float* __restrict__ wo) {
    const int b = blockIdx.z;
    mm384_tile(wo, g_T + (size_t)b * CDIM * CDIM, g_Cm + (size_t)b * CDIM * CDIM);
}

// ---------------------------------------------------------------------------
// Kernel 7: Y_b = C_b * X_b   (384 x 16384, K=384)
// 128x128 tile / 256 threads / 8x8 per thread / KT=16, reg-prefetch
// grid(128, 3, BATCH)
// ---------------------------------------------------------------------------
__global__ __launch_bounds__(256)
void out_kernel(const float* __restrict__ x, float* __restrict__ y) {
    const int b  = blockIdx.z;
    const int i0 = blockIdx.y * 128;
    const int j0 = blockIdx.x * 128;
    __shared__ float As[16][136];
    __shared__ float Bs[16][136];
    const float* Cb = g_Cm + (size_t)b * CDIM * CDIM;
    const float* xb = x + (size_t)b * CDIM * HWDIM;
    float* yb = y + (size_t)b * CDIM * HWDIM;

    const int t  = threadIdx.x;
    const int tx = t & 15, ty = t >> 4;

    const int mA0 = (t)       >> 2, kqA0 = ((t)       & 3) << 2;
    const int mA1 = (t + 256) >> 2, kqA1 = ((t + 256) & 3) << 2;
    const int kB0 = (t)       >> 5, nB0 = ((t)       & 31) << 2;
    const int kB1 = (t + 256) >> 5, nB1 = ((t + 256) & 31) << 2;

    float acc[8][8] = {};
    float4 pa0, pa1, pb0, pb1;

    pa0 = *(const float4*)&Cb[(i0 + mA0) * CDIM + kqA0];
    pa1 = *(const float4*)&Cb[(i0 + mA1) * CDIM + kqA1];
    pb0 = *(const float4*)&xb[(size_t)kB0 * HWDIM + j0 + nB0];
    pb1 = *(const float4*)&xb[(size_t)kB1 * HWDIM + j0 + nB1];

    for (int k0 = 0; k0 < CDIM; k0 += 16) {
        As[kqA0 + 0][mA0] = pa0.x; As[kqA0 + 1][mA0] = pa0.y;
        As[kqA0 + 2][mA0] = pa0.z; As[kqA0 + 3][mA0] = pa0.w;
        As[kqA1 + 0][mA1] = pa1.x; As[kqA1 + 1][mA1] = pa1.y;
        As[kqA1 + 2][mA1] = pa1.z; As[kqA1 + 3][mA1] = pa1.w;
        *(float4*)&Bs[kB0][nB0] = pb0;
        *(float4*)&Bs[kB1][nB1] = pb1;
        __syncthreads();

        int kn = k0 + 16;
        if (kn < CDIM) {
            pa0 = *(const float4*)&Cb[(i0 + mA0) * CDIM + kn + kqA0];
            pa1 = *(const float4*)&Cb[(i0 + mA1) * CDIM + kn + kqA1];
            pb0 = *(const float4*)&xb[(size_t)(kn + kB0) * HWDIM + j0 + nB0];
            pb1 = *(const float4*)&xb[(size_t)(kn + kB1) * HWDIM + j0 + nB1];
        }

        #pragma unroll
        for (int kk = 0; kk < 16; kk++) {
            float a[8], bv[8];
            #pragma unroll
            for (int i = 0; i < 8; i++) a[i]  = As[kk][ty + 16 * i];
            #pragma unroll
            for (int j = 0; j < 8; j++) bv[j] = Bs[kk][tx + 16 * j];
            #pragma unroll
            for (int i = 0; i < 8; i++)
                #pragma unroll
                for (int j = 0; j < 8; j++) acc[i][j] += a[i] * bv[j];
        }
        __syncthreads();
    }

    #pragma unroll
    for (int i = 0; i < 8; i++)
        #pragma unroll
        for (int j = 0; j < 8; j++)
            yb[(size_t)(i0 + ty + 16 * i) * HWDIM + j0 + tx + 16 * j] = acc[i][j];
}

// ---------------------------------------------------------------------------
extern "C" void kernel_launch(void* const* d_in, const int* in_sizes, int n_in,
                              void* d_out, int out_size) {
    const float* x    = (const float*)d_in[0];
    const float* wq   = (const float*)d_in[1];
    const float* wk   = (const float*)d_in[2];
    const float* wv   = (const float*)d_in[3];
    const float* wo   = (const float*)d_in[4];
    const float* temp = (const float*)d_in[5];
    float* y = (float*)d_out;

    dim3 blk16(16, 16);

    // 1. Gram partials (upper-tri tiles, split-K) + reduce/mirror
    gram_kernel<<<dim3(NTILE, 1, BATCH * KSPLIT), 256>>>(x);
    gram_reduce_kernel<<<dim3(NTILE * 16384 / 256, BATCH), 256>>>();

    // 2. Mq = Wq*G, Mk = Wk*G
    projG_kernel<<<dim3(6, 6, 2 * BATCH), blk16>>>(wq, wk);

    // 3. row norms
    norm_kernel<<<dim3(CDIM, BATCH, 2), 32>>>(wq, wk);

    // 4. attention + softmax
    attn_kernel<<<dim3(CH, HEADS, BATCH), 64>>>(wk, temp);

    // 5. T = blockdiag(A) * Wv
    tmat_kernel<<<dim3(6, HEADS, BATCH), dim3(64, 8)>>>(wv);

    // 6. C = Wo * T
    cmat_kernel<<<dim3(6, 6, BATCH), blk16>>>(wo);

    // 7. Y = C * X
    out_kernel<<<dim3(HWDIM / 128, 3, BATCH), 256>>>(x, y);
}

// round 17
// speedup vs baseline: 1.5338x; 1.5338x over previous
#include <cuda_runtime.h>
#include <cuda_bf16.h>
#include <mma.h>
#include <math.h>
#include <cstdint>

using namespace nvcuda;

#define BATCH 8
#define CDIM  384
#define HWDIM 16384
#define HEADS 8
#define CH    48
#define EPSV  1e-12f
#define KSPLIT 8
#define KCHUNK (HWDIM / KSPLIT)   // 2048
#define NTILE  6                  // upper-triangular 128x128 tiles of 3x3

// ---------------- device scratch (no runtime allocation allowed) ------------
__device__ float g_Gp[KSPLIT*BATCH*NTILE*128*128]; // split-K Gram partials
__device__ float g_G [BATCH*CDIM*CDIM];   // Gram matrices X X^T
__device__ float g_Mq[BATCH*CDIM*CDIM];   // Wq * G
__device__ float g_Mk[BATCH*CDIM*CDIM];   // Wk * G
__device__ float g_nq[BATCH*CDIM];        // q row norms
__device__ float g_nk[BATCH*CDIM];        // k row norms
__device__ float g_At[BATCH*HEADS*CH*CH]; // softmaxed attention blocks
__device__ float g_T [BATCH*CDIM*CDIM];   // blockdiag(A) * Wv

// bf16 hi/lo operands (X in NATIVE layout [b][c][hw]; C row-major)
__device__ __nv_bfloat16 g_Xhi[(size_t)BATCH*CDIM*HWDIM];
__device__ __nv_bfloat16 g_Xlo[(size_t)BATCH*CDIM*HWDIM];
__device__ __nv_bfloat16 g_Chi[BATCH*CDIM*CDIM];
__device__ __nv_bfloat16 g_Clo[BATCH*CDIM*CDIM];

__constant__ int c_ti[NTILE] = {0, 0, 0, 1, 1, 2};
__constant__ int c_tj[NTILE] = {0, 1, 2, 1, 2, 2};

// ---------------------------------------------------------------------------
// convX: X fp32 -> hi/lo bf16, native layout. float4 per thread.
// ---------------------------------------------------------------------------
__global__ void convX_kernel(const float* __restrict__ x) {
    const size_t N4 = (size_t)BATCH * CDIM * HWDIM / 4;
    size_t i4 = (size_t)blockIdx.x * 256 + threadIdx.x;
    if (i4 >= N4) return;
    float4 v = ((const float4*)x)[i4];
    __nv_bfloat16 h0 = __float2bfloat16(v.x);
    __nv_bfloat16 h1 = __float2bfloat16(v.y);
    __nv_bfloat16 h2 = __float2bfloat16(v.z);
    __nv_bfloat16 h3 = __float2bfloat16(v.w);
    __nv_bfloat162* hp = (__nv_bfloat162*)g_Xhi;
    __nv_bfloat162* lp = (__nv_bfloat162*)g_Xlo;
    hp[i4 * 2 + 0] = __nv_bfloat162(h0, h1);
    hp[i4 * 2 + 1] = __nv_bfloat162(h2, h3);
    lp[i4 * 2 + 0] = __nv_bfloat162(
        __float2bfloat16(v.x - __bfloat162float(h0)),
        __float2bfloat16(v.y - __bfloat162float(h1)));
    lp[i4 * 2 + 1] = __nv_bfloat162(
        __float2bfloat16(v.z - __bfloat162float(h2)),
        __float2bfloat16(v.w - __bfloat162float(h3)));
}

// ---------------------------------------------------------------------------
// Kernel 1 (WMMA): Gram partials via bf16 3-term split on tensor cores.
// grid(NTILE, 1, BATCH*KSPLIT), 256 threads (8 warps, warp tile 32x64)
// A rows = X[i0..i0+127][k] (row_major), B rows = X[j0..j0+127][k] (col_major)
// ---------------------------------------------------------------------------
__global__ __launch_bounds__(256)
void gram_mma_kernel() {
    const int tile = blockIdx.x;
    const int z    = blockIdx.z;           // b*KSPLIT + ks
    const int b    = z / KSPLIT;
    const int ks   = z % KSPLIT;
    const int i0   = c_ti[tile] * 128;
    const int j0   = c_tj[tile] * 128;
    const int kbeg = ks * KCHUNK;

    __shared__ __align__(16) __nv_bfloat16 Ahi[128][40], Alo[128][40];
    __shared__ __align__(16) __nv_bfloat16 Bhi[128][40], Blo[128][40];

    const __nv_bfloat16* Xh = g_Xhi + (size_t)b * CDIM * HWDIM;
    const __nv_bfloat16* Xl = g_Xlo + (size_t)b * CDIM * HWDIM;

    const int t   = threadIdx.x;
    const int wid = t >> 5;
    const int wm  = wid >> 1;          // 0..3, 32-row slab
    const int wn  = wid & 1;           // 0..1, 64-col slab

    wmma::fragment<wmma::accumulator, 16, 16, 16, float> acc[2][4];
    #pragma unroll
    for (int i = 0; i < 2; i++)
        #pragma unroll
        for (int j = 0; j < 4; j++) wmma::fill_fragment(acc[i][j], 0.f);

    for (int k0 = kbeg; k0 < kbeg + KCHUNK; k0 += 32) {
        __syncthreads();
        #pragma unroll
        for (int l = 0; l < 2; l++) {
            int q   = t + l * 256;          // 0..511
            int row = q >> 2;               // 0..127
            int c8  = (q & 3) * 8;          // 0,8,16,24
            *(uint4*)&Ahi[row][c8] = *(const uint4*)&Xh[(size_t)(i0 + row) * HWDIM + k0 + c8];
            *(uint4*)&Alo[row][c8] = *(const uint4*)&Xl[(size_t)(i0 + row) * HWDIM + k0 + c8];
            *(uint4*)&Bhi[row][c8] = *(const uint4*)&Xh[(size_t)(j0 + row) * HWDIM + k0 + c8];
            *(uint4*)&Blo[row][c8] = *(const uint4*)&Xl[(size_t)(j0 + row) * HWDIM + k0 + c8];
        }
        __syncthreads();

        #pragma unroll
        for (int s = 0; s < 2; s++) {
            const int kk = s * 16;
            wmma::fragment<wmma::matrix_a, 16, 16, 16, __nv_bfloat16, wmma::row_major> ah[2], al[2];
            #pragma unroll
            for (int i = 0; i < 2; i++) {
                wmma::load_matrix_sync(ah[i], &Ahi[wm * 32 + i * 16][kk], 40);
                wmma::load_matrix_sync(al[i], &Alo[wm * 32 + i * 16][kk], 40);
            }
            #pragma unroll
            for (int j = 0; j < 4; j++) {
                wmma::fragment<wmma::matrix_b, 16, 16, 16, __nv_bfloat16, wmma::col_major> bh, bl;
                wmma::load_matrix_sync(bh, &Bhi[wn * 64 + j * 16][kk], 40);
                wmma::load_matrix_sync(bl, &Blo[wn * 64 + j * 16][kk], 40);
                #pragma unroll
                for (int i = 0; i < 2; i++) {
                    wmma::mma_sync(acc[i][j], ah[i], bh, acc[i][j]);
                    wmma::mma_sync(acc[i][j], ah[i], bl, acc[i][j]);
                    wmma::mma_sync(acc[i][j], al[i], bh, acc[i][j]);
                }
            }
        }
    }

    float* Gp = g_Gp + ((size_t)z * NTILE + tile) * 16384;
    #pragma unroll
    for (int i = 0; i < 2; i++)
        #pragma unroll
        for (int j = 0; j < 4; j++)
            wmma::store_matrix_sync(&Gp[(wm * 32 + i * 16) * 128 + wn * 64 + j * 16],
                                    acc[i][j], 128, wmma::mem_row_major);
}

// ---------------------------------------------------------------------------
// Kernel 1b: reduce split-K partials, mirror to full symmetric G. (unchanged)
// ---------------------------------------------------------------------------
__global__ void gram_reduce_kernel() {
    const int b = blockIdx.y;
    const int gidx = blockIdx.x * 256 + threadIdx.x;
    const int tile = gidx >> 14;
    const int e    = gidx & 16383;
    const int r = e >> 7, c = e & 127;

    float s = 0.f;
    #pragma unroll
    for (int ks = 0; ks < KSPLIT; ks++)
        s += g_Gp[(((size_t)(b * KSPLIT + ks)) * NTILE + tile) * 16384 + e];

    const int i = c_ti[tile] * 128 + r;
    const int j = c_tj[tile] * 128 + c;
    float* Gb = g_G + (size_t)b * CDIM * CDIM;
    Gb[i * CDIM + j] = s;
    Gb[j * CDIM + i] = s;
}

// ---------------------------------------------------------------------------
// mm384: Out = A * B (384^3, fp32 SIMT) — unchanged, negligible cost
// ---------------------------------------------------------------------------
__device__ __forceinline__ void mm384_tile(const float* __restrict__ A,
                                           const float* __restrict__ Bm,
                                           float* __restrict__ Out) {
    __shared__ float As[16][68];
    __shared__ float Bs[16][68];
    const int tx = threadIdx.x, ty = threadIdx.y;
    const int flat = ty * 16 + tx;
    const int i0 = blockIdx.y * 64;
    const int j0 = blockIdx.x * 64;
    float acc[4][4] = {};

    for (int k0 = 0; k0 < CDIM; k0 += 16) {
        #pragma unroll
        for (int l = 0; l < 4; l++) {
            int idx = flat + l * 256;
            As[idx & 15][idx >> 4] = A[(i0 + (idx >> 4)) * CDIM + k0 + (idx & 15)];
            Bs[idx >> 6][idx & 63]  = Bm[(k0 + (idx >> 6)) * CDIM + j0 + (idx & 63)];
        }
        __syncthreads();
        #pragma unroll
        for (int kk = 0; kk < 16; kk++) {
            float a[4], bv[4];
            #pragma unroll
            for (int i = 0; i < 4; i++) a[i]  = As[kk][ty + 16 * i];
            #pragma unroll
            for (int j = 0; j < 4; j++) bv[j] = Bs[kk][tx + 16 * j];
            #pragma unroll
            for (int i = 0; i < 4; i++)
                #pragma unroll
                for (int j = 0; j < 4; j++) acc[i][j] += a[i] * bv[j];
        }
        __syncthreads();
    }
    #pragma unroll
    for (int i = 0; i < 4; i++)
        #pragma unroll
        for (int j = 0; j < 4; j++)
            Out[(i0 + ty + 16 * i) * CDIM + (j0 + tx + 16 * j)] = acc[i][j];
}

__global__ void projG_kernel(const float* __restrict__ wq,
                             const float* __restrict__ wk) {
    const int z = blockIdx.z;
    const int b = z >> 1, s = z & 1;
    const float* W   = s ? wk : wq;
    const float* Gb  = g_G + (size_t)b * CDIM * CDIM;
    float* Out = (s ? g_Mk : g_Mq) + (size_t)b * CDIM * CDIM;
    mm384_tile(W, Gb, Out);
}

__global__ void norm_kernel(const float* __restrict__ wq,
                            const float* __restrict__ wk) {
    const int i = blockIdx.x, b = blockIdx.y, s = blockIdx.z;
    const float* M = (s ? g_Mk : g_Mq) + ((size_t)b * CDIM + i) * CDIM;
    const float* W = (s ? wk : wq) + (size_t)i * CDIM;
    float sum = 0.f;
    for (int k = threadIdx.x; k < CDIM; k += 32) sum += M[k] * W[k];
    #pragma unroll
    for (int o = 16; o; o >>= 1) sum += __shfl_xor_sync(0xffffffffu, sum, o);
    if (threadIdx.x == 0) (s ? g_nk : g_nq)[b * CDIM + i] = sqrtf(sum);
}

__global__ void attn_kernel(const float* __restrict__ wk,
                            const float* __restrict__ temp) {
    const int i = blockIdx.x, h = blockIdx.y, b = blockIdx.z;
    const int ig = h * CH + i;
    __shared__ float mrow[CDIM];
    __shared__ float sl[CH];
    __shared__ float red[2];
    const float* Mq = g_Mq + ((size_t)b * CDIM + ig) * CDIM;
    for (int k = threadIdx.x; k < CDIM; k += 64) mrow[k] = Mq[k];
    __syncthreads();

    const int j = threadIdx.x;
    if (j < CH) {
        const int jg = h * CH + j;
        const float* wkr = wk + (size_t)jg * CDIM;
        float s = 0.f;
        #pragma unroll 8
        for (int k = 0; k < CDIM; k++) s += mrow[k] * wkr[k];
        float nq = fmaxf(g_nq[b * CDIM + ig], EPSV);
        float nk = fmaxf(g_nk[b * CDIM + jg], EPSV);
        sl[j] = s / (nq * nk) * temp[h];
    }
    __syncthreads();
    if (threadIdx.x == 0) {
        float m = -1e30f;
        for (int jj = 0; jj < CH; jj++) m = fmaxf(m, sl[jj]);
        float sum = 0.f;
        for (int jj = 0; jj < CH; jj++) sum += expf(sl[jj] - m);
        red[0] = m;
        red[1] = 1.f / sum;
    }
    __syncthreads();
    if (j < CH)
        g_At[(((size_t)b * HEADS + h) * CH + i) * CH + j] =
            expf(sl[j] - red[0]) * red[1];
}

__global__ void tmat_kernel(const float* __restrict__ wv) {
    const int c0 = blockIdx.x * 64, h = blockIdx.y, b = blockIdx.z;
    __shared__ float As[CH][CH];
    __shared__ float Vs[CH][64];
    const int tid = threadIdx.y * 64 + threadIdx.x;
    const float* Ab = g_At + (size_t)(b * HEADS + h) * CH * CH;
    for (int idx = tid; idx < CH * CH; idx += 512)
        As[idx / CH][idx % CH] = Ab[idx];
    for (int idx = tid; idx < CH * 64; idx += 512) {
        int jj = idx >> 6, c = idx & 63;
        Vs[jj][c] = wv[(size_t)(h * CH + jj) * CDIM + c0 + c];
    }
    __syncthreads();
    const int c = threadIdx.x;
    for (int i = threadIdx.y; i < CH; i += 8) {
        float s = 0.f;
        #pragma unroll
        for (int jj = 0; jj < CH; jj++) s += As[i][jj] * Vs[jj][c];
        g_T[((size_t)b * CDIM + h * CH + i) * CDIM + c0 + c] = s;
    }
}

// ---------------------------------------------------------------------------
// Kernel 6 (fused): C = Wo * T_b, emitting bf16 hi/lo directly.
// Same tile math as mm384_tile; epilogue does the convC split in-register.
// grid(6,6,BATCH), block(16,16)
// ---------------------------------------------------------------------------
__global__ void cmat_kernel(const float* __restrict__ wo) {
    const int b = blockIdx.z;
    const float* A  = wo;
    const float* Bm = g_T + (size_t)b * CDIM * CDIM;

    __shared__ float As[16][68];
    __shared__ float Bs[16][68];
    const int tx = threadIdx.x, ty = threadIdx.y;
    const int flat = ty * 16 + tx;
    const int i0 = blockIdx.y * 64;
    const int j0 = blockIdx.x * 64;
    float acc[4][4] = {};

    for (int k0 = 0; k0 < CDIM; k0 += 16) {
        #pragma unroll
        for (int l = 0; l < 4; l++) {
            int idx = flat + l * 256;
            As[idx & 15][idx >> 4] = A[(i0 + (idx >> 4)) * CDIM + k0 + (idx & 15)];
            Bs[idx >> 6][idx & 63]  = Bm[(k0 + (idx >> 6)) * CDIM + j0 + (idx & 63)];
        }
        __syncthreads();
        #pragma unroll
        for (int kk = 0; kk < 16; kk++) {
            float a[4], bv[4];
            #pragma unroll
            for (int i = 0; i < 4; i++) a[i]  = As[kk][ty + 16 * i];
            #pragma unroll
            for (int j = 0; j < 4; j++) bv[j] = Bs[kk][tx + 16 * j];
            #pragma unroll
            for (int i = 0; i < 4; i++)
                #pragma unroll
                for (int j = 0; j < 4; j++) acc[i][j] += a[i] * bv[j];
        }
        __syncthreads();
    }

    __nv_bfloat16* Chi = g_Chi + (size_t)b * CDIM * CDIM;
    __nv_bfloat16* Clo = g_Clo + (size_t)b * CDIM * CDIM;
    #pragma unroll
    for (int i = 0; i < 4; i++)
        #pragma unroll
        for (int j = 0; j < 4; j++) {
            float v = acc[i][j];
            __nv_bfloat16 hi = __float2bfloat16(v);
            int o = (i0 + ty + 16 * i) * CDIM + (j0 + tx + 16 * j);
            Chi[o] = hi;
            Clo[o] = __float2bfloat16(v - __bfloat162float(hi));
        }
}

// ---------------------------------------------------------------------------
// Kernel 7 (WMMA): Y_b = C_b * X_b via bf16 3-term split on tensor cores.
// grid(HWDIM/128, 3, BATCH), 256 threads (8 warps, warp tile 32x64)
// A = C rows (row_major, lda CDIM); B = X native [k][n] (row_major, ldb HWDIM)
// ---------------------------------------------------------------------------
__global__ __launch_bounds__(256)
void out_mma_kernel(float* __restrict__ y) {
    const int nj = blockIdx.x, mi = blockIdx.y, b = blockIdx.z;

    __shared__ __align__(16) __nv_bfloat16 Ahi[128][40], Alo[128][40];
    __shared__ __align__(16) __nv_bfloat16 Bhi[32][136], Blo[32][136];

    const __nv_bfloat16* Ch = g_Chi + (size_t)b * CDIM * CDIM;
    const __nv_bfloat16* Cl = g_Clo + (size_t)b * CDIM * CDIM;
    const __nv_bfloat16* Xh = g_Xhi + (size_t)b * CDIM * HWDIM;
    const __nv_bfloat16* Xl = g_Xlo + (size_t)b * CDIM * HWDIM;

    const int t   = threadIdx.x;
    const int wid = t >> 5;
    const int wm  = wid >> 1;
    const int wn  = wid & 1;
    const int n0  = nj * 128;
    const int m0  = mi * 128;

    wmma::fragment<wmma::accumulator, 16, 16, 16, float> acc[2][4];
    #pragma unroll
    for (int i = 0; i < 2; i++)
        #pragma unroll
        for (int j = 0; j < 4; j++) wmma::fill_fragment(acc[i][j], 0.f);

    for (int k0 = 0; k0 < CDIM; k0 += 32) {
        __syncthreads();
        #pragma unroll
        for (int l = 0; l < 2; l++) {
            int q = t + l * 256;
            {   // A tile 128x32: 4 uint4 per row
                int row = q >> 2, c8 = (q & 3) * 8;
                *(uint4*)&Ahi[row][c8] = *(const uint4*)&Ch[(size_t)(m0 + row) * CDIM + k0 + c8];
                *(uint4*)&Alo[row][c8] = *(const uint4*)&Cl[(size_t)(m0 + row) * CDIM + k0 + c8];
            }
            {   // B tile 32x128: 16 uint4 per row
                int row = q >> 4, c8 = (q & 15) * 8;
                *(uint4*)&Bhi[row][c8] = *(const uint4*)&Xh[(size_t)(k0 + row) * HWDIM + n0 + c8];
                *(uint4*)&Blo[row][c8] = *(const uint4*)&Xl[(size_t)(k0 + row) * HWDIM + n0 + c8];
            }
        }
        __syncthreads();

        #pragma unroll
        for (int s = 0; s < 2; s++) {
            const int kk = s * 16;
            wmma::fragment<wmma::matrix_a, 16, 16, 16, __nv_bfloat16, wmma::row_major> ah[2], al[2];
            #pragma unroll
            for (int i = 0; i < 2; i++) {
                wmma::load_matrix_sync(ah[i], &Ahi[wm * 32 + i * 16][kk], 40);
                wmma::load_matrix_sync(al[i], &Alo[wm * 32 + i * 16][kk], 40);
            }
            #pragma unroll
            for (int j = 0; j < 4; j++) {
                wmma::fragment<wmma::matrix_b, 16, 16, 16, __nv_bfloat16, wmma::row_major> bh, bl;
                wmma::load_matrix_sync(bh, &Bhi[kk][wn * 64 + j * 16], 136);
                wmma::load_matrix_sync(bl, &Blo[kk][wn * 64 + j * 16], 136);
                #pragma unroll
                for (int i = 0; i < 2; i++) {
                    wmma::mma_sync(acc[i][j], ah[i], bh, acc[i][j]);
                    wmma::mma_sync(acc[i][j], ah[i], bl, acc[i][j]);
                    wmma::mma_sync(acc[i][j], al[i], bh, acc[i][j]);
                }
            }
        }
    }

    float* yb = y + (size_t)b * CDIM * HWDIM;
    #pragma unroll
    for (int i = 0; i < 2; i++)
        #pragma unroll
        for (int j = 0; j < 4; j++)
            wmma::store_matrix_sync(
                &yb[(size_t)(m0 + wm * 32 + i * 16) * HWDIM + n0 + wn * 64 + j * 16],
                acc[i][j], HWDIM, wmma::mem_row_major);
}

// ---------------------------------------------------------------------------
extern "C" void kernel_launch(void* const* d_in, const int* in_sizes, int n_in,
                              void* d_out, int out_size) {
    const float* x    = (const float*)d_in[0];
    const float* wq   = (const float*)d_in[1];
    const float* wk   = (const float*)d_in[2];
    const float* wv   = (const float*)d_in[3];
    const float* wo   = (const float*)d_in[4];
    const float* temp = (const float*)d_in[5];
    float* y = (float*)d_out;

    dim3 blk16(16, 16);

    // 0. X -> bf16 hi/lo (native layout; feeds both tensor GEMMs)
    const size_t N4 = (size_t)BATCH * CDIM * HWDIM / 4;
    convX_kernel<<<(unsigned)((N4 + 255) / 256), 256>>>(x);

    // 1. Gram partials (tensor cores) + reduce/mirror
    gram_mma_kernel<<<dim3(NTILE, 1, BATCH * KSPLIT), 256>>>();
    gram_reduce_kernel<<<dim3(NTILE * 16384 / 256, BATCH), 256>>>();

    // 2-5. middle chain (384^3-scale, fp32 SIMT)
    projG_kernel<<<dim3(6, 6, 2 * BATCH), blk16>>>(wq, wk);
    norm_kernel<<<dim3(CDIM, BATCH, 2), 32>>>(wq, wk);
    attn_kernel<<<dim3(CH, HEADS, BATCH), 64>>>(wk, temp);
    tmat_kernel<<<dim3(6, HEADS, BATCH), dim3(64, 8)>>>(wv);

    // 6. C = Wo * T with fused bf16 hi/lo epilogue
    cmat_kernel<<<dim3(6, 6, BATCH), blk16>>>(wo);

    // 7. Y = C * X (tensor cores)
    out_mma_kernel<<<dim3(HWDIM / 128, 3, BATCH), 256>>>(y);
}